// round 15
// baseline (speedup 1.0000x reference)
#include <cuda_runtime.h>

// BranchRoute: score = sigmoid(x @ gate_w + gate_b); mask_i = score_i > 0.5
// out = concat(x*m0, x*m1, x*(m0+m1)), each [N, D] fp32.
// sigmoid(z) > 0.5 <=> z > 0, so only the dot-product sign matters.
//
// R15: final block-size point. Bench curve: 128thr: 87.5us, 256: 85.2,
// 512: 84.5 (best, DRAM 74.2% = ceiling). 1024 threads/block, one
// row/block, grid=8192: 1x LDG.128 (x) + 2x LDG.128 (gate) + 3x STG.128
// per thread, ~26 regs, reduce across 32 warps. Minimal per-block serial
// window; DRAM ceiling unchanged.

#define THREADS 1024
#define DIM 4096

__global__ void __launch_bounds__(THREADS)
branch_route_kernel(const float* __restrict__ x,
                    const float* __restrict__ gw,   // [D, 2]
                    const float* __restrict__ gb,   // [2]
                    float* __restrict__ out,        // [3, N, D]
                    int N)
{
    const int t = threadIdx.x;
    const int row = blockIdx.x;

    // Gate pairs for this thread's 4 columns (4t..4t+3): 2 x LDG.128 (L2).
    float4 wa, wb;
    {
        const float4* gw4 = (const float4*)gw;   // 2 col-pairs per float4
        const int q = (t * 4) >> 1;              // float4 index
        wa = __ldg(&gw4[q + 0]);                 // cols 4t+0, 4t+1
        wb = __ldg(&gw4[q + 1]);                 // cols 4t+2, 4t+3
    }

    // Row chunk: 1 x LDG.128.
    const float4* xr = (const float4*)(x + (size_t)row * DIM);
    const float4 v = xr[t];

    // Partial dot.
    float s0 = 0.f, s1 = 0.f;
    s0 = fmaf(v.x, wa.x, s0);  s1 = fmaf(v.x, wa.y, s1);
    s0 = fmaf(v.y, wa.z, s0);  s1 = fmaf(v.y, wa.w, s1);
    s0 = fmaf(v.z, wb.x, s0);  s1 = fmaf(v.z, wb.y, s1);
    s0 = fmaf(v.w, wb.z, s0);  s1 = fmaf(v.w, wb.w, s1);

    // Warp butterfly reduce.
#pragma unroll
    for (int o = 16; o > 0; o >>= 1) {
        s0 += __shfl_xor_sync(0xffffffffu, s0, o);
        s1 += __shfl_xor_sync(0xffffffffu, s1, o);
    }

    __shared__ __align__(16) float2 red[32];
    if ((t & 31) == 0) red[t >> 5] = make_float2(s0, s1);
    __syncthreads();

    float d0 = gb[0], d1 = gb[1];
#pragma unroll
    for (int k = 0; k < 16; k++) {
        const float4 r = ((const float4*)red)[k];   // two partials per LDS.128
        d0 += r.x + r.z;
        d1 += r.y + r.w;
    }

    const float f0 = d0 > 0.f ? 1.f : 0.f;
    const float f1 = d1 > 0.f ? 1.f : 0.f;
    const float fc = f0 + f1;

    const size_t base = (size_t)row * (DIM / 4) + t;
    float4* __restrict__ p0 = (float4*)out + base;
    float4* __restrict__ p1 = (float4*)out + (size_t)N * (DIM / 4) + base;
    float4* __restrict__ pc = (float4*)out + (size_t)2 * N * (DIM / 4) + base;

    float4 a, b, s;
    a.x = f0 * v.x; a.y = f0 * v.y; a.z = f0 * v.z; a.w = f0 * v.w;
    b.x = f1 * v.x; b.y = f1 * v.y; b.z = f1 * v.z; b.w = f1 * v.w;
    s.x = fc * v.x; s.y = fc * v.y; s.z = fc * v.z; s.w = fc * v.w;
    *p0 = a;
    *p1 = b;
    *pc = s;
}

extern "C" void kernel_launch(void* const* d_in, const int* in_sizes, int n_in,
                              void* d_out, int out_size)
{
    const float* x  = (const float*)d_in[0];
    const float* gw = (const float*)d_in[1];
    const float* gb = (const float*)d_in[2];
    float* out = (float*)d_out;

    const int N = in_sizes[0] / DIM;   // 8192

    // One row per block, 1024 threads.
    branch_route_kernel<<<N, THREADS>>>(x, gw, gb, out, N);
}

// round 16
// speedup vs baseline: 1.3792x; 1.3792x over previous
#include <cuda_runtime.h>

// BranchRoute: score = sigmoid(x @ gate_w + gate_b); mask_i = score_i > 0.5
// out = concat(x*m0, x*m1, x*(m0+m1)), each [N, D] fp32.
// sigmoid(z) > 0.5 <=> z > 0, so only the dot-product sign matters.
//
// FINAL (= R14, measured best: bench 84.5us, kernel 81.3us, DRAM 74.2%).
// 15 rounds of single-variable isolation established:
//  - DRAM is pinned at ~74% (5.88 TB/s) for this 1R:3W interleaved stream:
//    the HBM mixed-stream efficiency ceiling. No SM-side lever moves it
//    (occupancy 24-90%, cache policies, prefetch, TMA bulk stores, store
//    grouping, 64/128/256-bit widths, issue order all isolated).
//  - Block-size curve unimodal: 128:87.5 / 256:85.2 / 512:84.5 / 1024:116.9.
//  - Grid curve favors max oversubscription (one row per block, grid=N).
//  - Gate loads as LDG.128 (R11) was the one real win: fewer L1tex
//    wavefronts competing with the store stream.
// Config: 512 thr/block, one row/block, grid=8192, 32 regs, occ 90%.

#define THREADS 512
#define DIM 4096
#define CHUNKS 2   // float4s per thread = 4096 / (512*4)

__global__ void __launch_bounds__(THREADS)
branch_route_kernel(const float* __restrict__ x,
                    const float* __restrict__ gw,   // [D, 2]
                    const float* __restrict__ gb,   // [2]
                    float* __restrict__ out,        // [3, N, D]
                    int N)
{
    const int t = threadIdx.x;
    const int row = blockIdx.x;

    // Gate pairs for this thread's 8 columns: 4 x LDG.128 (L2-resident).
    // Thread owns columns {c*2048 + 4t + j : c in 0..1, j in 0..3}.
    float4 wv[4];
    {
        const float4* gw4 = (const float4*)gw;   // 2 col-pairs per float4
#pragma unroll
        for (int c = 0; c < CHUNKS; c++) {
            const int q = (c * 2048 + t * 4) >> 1;   // float4 index
            wv[c * 2 + 0] = __ldg(&gw4[q + 0]);      // cols 4t+0, 4t+1
            wv[c * 2 + 1] = __ldg(&gw4[q + 1]);      // cols 4t+2, 4t+3
        }
    }

    // Row chunk: 2 x LDG.128.
    const float4* xr = (const float4*)(x + (size_t)row * DIM);
    float4 v[CHUNKS];
#pragma unroll
    for (int c = 0; c < CHUNKS; c++) v[c] = xr[c * THREADS + t];

    // Partial dots.
    float s0 = 0.f, s1 = 0.f;
#pragma unroll
    for (int c = 0; c < CHUNKS; c++) {
        const float4 wa = wv[c * 2 + 0];
        const float4 wb = wv[c * 2 + 1];
        s0 = fmaf(v[c].x, wa.x, s0);  s1 = fmaf(v[c].x, wa.y, s1);
        s0 = fmaf(v[c].y, wa.z, s0);  s1 = fmaf(v[c].y, wa.w, s1);
        s0 = fmaf(v[c].z, wb.x, s0);  s1 = fmaf(v[c].z, wb.y, s1);
        s0 = fmaf(v[c].w, wb.z, s0);  s1 = fmaf(v[c].w, wb.w, s1);
    }

    // Warp butterfly reduce.
#pragma unroll
    for (int o = 16; o > 0; o >>= 1) {
        s0 += __shfl_xor_sync(0xffffffffu, s0, o);
        s1 += __shfl_xor_sync(0xffffffffu, s1, o);
    }

    __shared__ __align__(16) float2 red[16];
    if ((t & 31) == 0) red[t >> 5] = make_float2(s0, s1);
    __syncthreads();

    float d0 = gb[0], d1 = gb[1];
#pragma unroll
    for (int k = 0; k < 8; k++) {
        const float4 r = ((const float4*)red)[k];   // two partials per LDS.128
        d0 += r.x + r.z;
        d1 += r.y + r.w;
    }

    const float f0 = d0 > 0.f ? 1.f : 0.f;
    const float f1 = d1 > 0.f ? 1.f : 0.f;
    const float fc = f0 + f1;

    const size_t base = (size_t)row * (DIM / 4);
    float4* __restrict__ p0 = (float4*)out + base;
    float4* __restrict__ p1 = (float4*)out + (size_t)N * (DIM / 4) + base;
    float4* __restrict__ pc = (float4*)out + (size_t)2 * N * (DIM / 4) + base;

#pragma unroll
    for (int c = 0; c < CHUNKS; c++) {
        const int idx = c * THREADS + t;
        float4 a, b, s;
        a.x = f0 * v[c].x; a.y = f0 * v[c].y; a.z = f0 * v[c].z; a.w = f0 * v[c].w;
        b.x = f1 * v[c].x; b.y = f1 * v[c].y; b.z = f1 * v[c].z; b.w = f1 * v[c].w;
        s.x = fc * v[c].x; s.y = fc * v[c].y; s.z = fc * v[c].z; s.w = fc * v[c].w;
        p0[idx] = a;
        p1[idx] = b;
        pc[idx] = s;
    }
}

extern "C" void kernel_launch(void* const* d_in, const int* in_sizes, int n_in,
                              void* d_out, int out_size)
{
    const float* x  = (const float*)d_in[0];
    const float* gw = (const float*)d_in[1];
    const float* gb = (const float*)d_in[2];
    float* out = (float*)d_out;

    const int N = in_sizes[0] / DIM;   // 8192

    // One row per block, 512 threads (measured optimum).
    branch_route_kernel<<<N, THREADS>>>(x, gw, gb, out, N);
}

// round 17
// speedup vs baseline: 1.3902x; 1.0080x over previous
#include <cuda_runtime.h>

// BranchRoute: score = sigmoid(x @ gate_w + gate_b); mask_i = score_i > 0.5
// out = concat(x*m0, x*m1, x*(m0+m1)), each [N, D] fp32.
// sigmoid(z) > 0.5 <=> z > 0, so only the dot-product sign matters.
//
// R17 = R14 (measured best, twice: 84.5/84.7us, DRAM ~74%) with ONE change:
// __stwt (st.global.wt) write-through stores — the last untested cache
// policy. Hypothesis: writeback L2 accumulates ~120MB dirty lines that
// evict in bursty trains against the read stream each graph replay;
// write-through drains continuously, smoothing the DRAM-visible mix.
// Config otherwise identical: 512 thr/block, one row/block, grid=8192.

#define THREADS 512
#define DIM 4096
#define CHUNKS 2   // float4s per thread = 4096 / (512*4)

__global__ void __launch_bounds__(THREADS)
branch_route_kernel(const float* __restrict__ x,
                    const float* __restrict__ gw,   // [D, 2]
                    const float* __restrict__ gb,   // [2]
                    float* __restrict__ out,        // [3, N, D]
                    int N)
{
    const int t = threadIdx.x;
    const int row = blockIdx.x;

    // Gate pairs for this thread's 8 columns: 4 x LDG.128 (L2-resident).
    float4 wv[4];
    {
        const float4* gw4 = (const float4*)gw;   // 2 col-pairs per float4
#pragma unroll
        for (int c = 0; c < CHUNKS; c++) {
            const int q = (c * 2048 + t * 4) >> 1;   // float4 index
            wv[c * 2 + 0] = __ldg(&gw4[q + 0]);      // cols 4t+0, 4t+1
            wv[c * 2 + 1] = __ldg(&gw4[q + 1]);      // cols 4t+2, 4t+3
        }
    }

    // Row chunk: 2 x LDG.128.
    const float4* xr = (const float4*)(x + (size_t)row * DIM);
    float4 v[CHUNKS];
#pragma unroll
    for (int c = 0; c < CHUNKS; c++) v[c] = xr[c * THREADS + t];

    // Partial dots.
    float s0 = 0.f, s1 = 0.f;
#pragma unroll
    for (int c = 0; c < CHUNKS; c++) {
        const float4 wa = wv[c * 2 + 0];
        const float4 wb = wv[c * 2 + 1];
        s0 = fmaf(v[c].x, wa.x, s0);  s1 = fmaf(v[c].x, wa.y, s1);
        s0 = fmaf(v[c].y, wa.z, s0);  s1 = fmaf(v[c].y, wa.w, s1);
        s0 = fmaf(v[c].z, wb.x, s0);  s1 = fmaf(v[c].z, wb.y, s1);
        s0 = fmaf(v[c].w, wb.z, s0);  s1 = fmaf(v[c].w, wb.w, s1);
    }

    // Warp butterfly reduce.
#pragma unroll
    for (int o = 16; o > 0; o >>= 1) {
        s0 += __shfl_xor_sync(0xffffffffu, s0, o);
        s1 += __shfl_xor_sync(0xffffffffu, s1, o);
    }

    __shared__ __align__(16) float2 red[16];
    if ((t & 31) == 0) red[t >> 5] = make_float2(s0, s1);
    __syncthreads();

    float d0 = gb[0], d1 = gb[1];
#pragma unroll
    for (int k = 0; k < 8; k++) {
        const float4 r = ((const float4*)red)[k];   // two partials per LDS.128
        d0 += r.x + r.z;
        d1 += r.y + r.w;
    }

    const float f0 = d0 > 0.f ? 1.f : 0.f;
    const float f1 = d1 > 0.f ? 1.f : 0.f;
    const float fc = f0 + f1;

    const size_t base = (size_t)row * (DIM / 4);
    float4* __restrict__ p0 = (float4*)out + base;
    float4* __restrict__ p1 = (float4*)out + (size_t)N * (DIM / 4) + base;
    float4* __restrict__ pc = (float4*)out + (size_t)2 * N * (DIM / 4) + base;

#pragma unroll
    for (int c = 0; c < CHUNKS; c++) {
        const int idx = c * THREADS + t;
        float4 a, b, s;
        a.x = f0 * v[c].x; a.y = f0 * v[c].y; a.z = f0 * v[c].z; a.w = f0 * v[c].w;
        b.x = f1 * v[c].x; b.y = f1 * v[c].y; b.z = f1 * v[c].z; b.w = f1 * v[c].w;
        s.x = fc * v[c].x; s.y = fc * v[c].y; s.z = fc * v[c].z; s.w = fc * v[c].w;
        __stwt(&p0[idx], a);
        __stwt(&p1[idx], b);
        __stwt(&pc[idx], s);
    }
}

extern "C" void kernel_launch(void* const* d_in, const int* in_sizes, int n_in,
                              void* d_out, int out_size)
{
    const float* x  = (const float*)d_in[0];
    const float* gw = (const float*)d_in[1];
    const float* gb = (const float*)d_in[2];
    float* out = (float*)d_out;

    const int N = in_sizes[0] / DIM;   // 8192

    // One row per block, 512 threads (measured optimum).
    branch_route_kernel<<<N, THREADS>>>(x, gw, gb, out, N);
}